// round 16
// baseline (speedup 1.0000x reference)
#include <cuda_runtime.h>
#include <cuda_fp16.h>
#include <cstdint>

#define NN 50000
#define EE 800000
#define HH 128
#define GG 256
#define SCHUNK 512
#define MAXNB 128   // >= ceil(NN/SCHUNK)=98
#define MAXT  512   // >= ceil(NN/128)=391 tile counters

// ---------------- scratch (device globals: no allocation allowed) -----------
__device__ __align__(16) __half g_zwh[NN * HH];   // dinv-scaled z @ W (fp16)
__device__ __align__(16) __half g_z1h[NN * HH];   // layer-1 activation (fp16)
__device__ __align__(16) __half g_W0h[HH * HH];   // W0 transposed [n][k] fp16
__device__ __align__(16) __half g_W1h[HH * HH];   // W1 transposed [n][k] fp16
__device__ __align__(16) float g_dinv[NN];        // 1/sqrt(deg)
__device__ __align__(16) int   g_cnt[NN];         // degree histogram (0 at launch entry)
__device__ __align__(16) int   g_cur[NN];         // fill cursor
__device__ __align__(16) int   g_rowptr[NN + 1];  // CSR row pointers (by dst)
__device__ __align__(16) int   g_col[EE];         // CSR column (src) — int4-read!
__device__ __align__(16) int   g_bsum[MAXNB];     // per-chunk sums
__device__ __align__(16) int   g_tile_cnt[MAXT];  // gather->gemm1 tile deps (0 at entry)
__device__ int   g_scan_ctr;        // scan-internal barrier (0 at launch entry)
__device__ int   g_scan_done;       // scan-complete counter (0 at launch entry)

// ---------------- fp16 MMA helper ----------------------------------------------
__device__ __forceinline__ void mma_f16(float c[4],
                                        uint32_t a0, uint32_t a1,
                                        uint32_t a2, uint32_t a3,
                                        uint32_t b0, uint32_t b1) {
    asm volatile(
        "mma.sync.aligned.m16n8k16.row.col.f32.f16.f16.f32 "
        "{%0,%1,%2,%3}, {%4,%5,%6,%7}, {%8,%9}, {%0,%1,%2,%3};"
        : "+f"(c[0]), "+f"(c[1]), "+f"(c[2]), "+f"(c[3])
        : "r"(a0), "r"(a1), "r"(a2), "r"(a3), "r"(b0), "r"(b1));
}

// ---------------- chunked fp16 GEMM body (A fp32 or fp16) -----------------------
template <bool AHALF>
__device__ __forceinline__ void gemm_body_chunked(
    __half (*As)[40], __half (*Bs)[40],
    const float* __restrict__ Af, const __half* __restrict__ Ah,
    const __half* __restrict__ Wh,
    __half* __restrict__ C, int n, int m0) {
    int tid = threadIdx.x;
    int lane = tid & 31, wid = tid >> 5;
    int wm = wid >> 1;
    int wn = wid & 1;

    float acc[2][8][4];
    #pragma unroll
    for (int ms = 0; ms < 2; ms++)
        #pragma unroll
        for (int nt = 0; nt < 8; nt++)
            #pragma unroll
            for (int j = 0; j < 4; j++) acc[ms][nt][j] = 0.0f;

    int rq = lane >> 2;
    int kq = (lane & 3) * 2;

    for (int k0 = 0; k0 < 128; k0 += 32) {
        #pragma unroll
        for (int it = 0; it < 2; it++) {
            int f = tid + 256 * it;
            int row = f >> 2;
            int k8 = (f & 3) * 8;
            int rg = m0 + row;
            if (rg >= n) rg = n - 1;
            if (AHALF) {
                uint4 v = *(const uint4*)&Ah[(size_t)rg * 128 + k0 + k8];
                *(uint4*)&As[row][k8] = v;
            } else {
                float4 a0 = *(const float4*)&Af[(size_t)rg * 128 + k0 + k8];
                float4 a1 = *(const float4*)&Af[(size_t)rg * 128 + k0 + k8 + 4];
                __half2 h[4];
                h[0] = __floats2half2_rn(a0.x, a0.y);
                h[1] = __floats2half2_rn(a0.z, a0.w);
                h[2] = __floats2half2_rn(a1.x, a1.y);
                h[3] = __floats2half2_rn(a1.z, a1.w);
                *(uint4*)&As[row][k8] = *(uint4*)h;
            }
        }
        #pragma unroll
        for (int it = 0; it < 2; it++) {
            int f = tid + 256 * it;
            int nr = f >> 2;
            int k8 = (f & 3) * 8;
            uint4 v = *(const uint4*)&Wh[(size_t)nr * 128 + k0 + k8];
            *(uint4*)&Bs[nr][k8] = v;
        }
        __syncthreads();

        #pragma unroll
        for (int kk = 0; kk < 32; kk += 16) {
            uint32_t a[2][4];
            #pragma unroll
            for (int ms = 0; ms < 2; ms++) {
                int r = wm * 32 + ms * 16 + rq;
                a[ms][0] = *(const uint32_t*)&As[r][kk + kq];
                a[ms][1] = *(const uint32_t*)&As[r + 8][kk + kq];
                a[ms][2] = *(const uint32_t*)&As[r][kk + kq + 8];
                a[ms][3] = *(const uint32_t*)&As[r + 8][kk + kq + 8];
            }
            #pragma unroll
            for (int nt = 0; nt < 8; nt++) {
                int nc = wn * 64 + nt * 8 + rq;
                uint32_t b0 = *(const uint32_t*)&Bs[nc][kk + kq];
                uint32_t b1 = *(const uint32_t*)&Bs[nc][kk + kq + 8];
                #pragma unroll
                for (int ms = 0; ms < 2; ms++)
                    mma_f16(acc[ms][nt], a[ms][0], a[ms][1], a[ms][2], a[ms][3], b0, b1);
            }
        }
        __syncthreads();
    }

    __half2* Ch = (__half2*)C;
    #pragma unroll
    for (int ms = 0; ms < 2; ms++) {
        int r0 = m0 + wm * 32 + ms * 16 + rq;
        float di0 = (r0 < n) ? g_dinv[r0] : 0.0f;
        float di8 = (r0 + 8 < n) ? g_dinv[r0 + 8] : 0.0f;
        #pragma unroll
        for (int nt = 0; nt < 8; nt++) {
            int nc = wn * 64 + nt * 8 + (lane & 3) * 2;
            if (r0 < n)
                Ch[(size_t)r0 * 64 + (nc >> 1)] =
                    __floats2half2_rn(di0 * acc[ms][nt][0], di0 * acc[ms][nt][1]);
            if (r0 + 8 < n)
                Ch[(size_t)(r0 + 8) * 64 + (nc >> 1)] =
                    __floats2half2_rn(di8 * acc[ms][nt][2], di8 * acc[ms][nt][3]);
        }
    }
}

// ---------------- gather body (dinv-scaled fp16 in, bias+PReLU+pool) ------------
// Writes z1h (fp16) when OUTHALF, else fp32 out. Returns after pool reduce.
template <bool OUTHALF>
__device__ __forceinline__ void gather_body(
    const __half* __restrict__ zws,
    const float* __restrict__ bias,
    const float* __restrict__ alpha,
    const int* __restrict__ batch,
    void* __restrict__ zout,
    float* __restrict__ pool,
    int n, int bid,
    float (*sred)[132], int* sgi) {
    int wid = threadIdx.x >> 5, lane = threadIdx.x & 31;
    int i = bid * 8 + wid;
    bool valid = i < n;

    float z0 = 0.f, z1 = 0.f, z2 = 0.f, z3 = 0.f;
    int gi = -1;

    if (valid) {
        const uint2* __restrict__ zwv = (const uint2*)zws;
        float di = g_dinv[i];

        uint2 sv = zwv[(size_t)i * 32 + lane];
        float2 f0 = __half22float2(*(const __half2*)&sv.x);
        float2 f1 = __half22float2(*(const __half2*)&sv.y);
        float4 acc = {f0.x, f0.y, f1.x, f1.y};

        int e0 = g_rowptr[i], e1 = g_rowptr[i + 1];
        int e = e0;
        for (; e < e1 && (e & 3); e++) {
            int s = g_col[e];
            uint2 u = zwv[(size_t)s * 32 + lane];
            float2 a = __half22float2(*(const __half2*)&u.x);
            float2 c = __half22float2(*(const __half2*)&u.y);
            acc.x += a.x; acc.y += a.y; acc.z += c.x; acc.w += c.y;
        }
        for (; e + 8 <= e1; e += 8) {
            int4 cA = *(const int4*)&g_col[e];
            int4 cB = *(const int4*)&g_col[e + 4];
            uint2 u0 = zwv[(size_t)cA.x * 32 + lane];
            uint2 u1 = zwv[(size_t)cA.y * 32 + lane];
            uint2 u2 = zwv[(size_t)cA.z * 32 + lane];
            uint2 u3 = zwv[(size_t)cA.w * 32 + lane];
            uint2 u4 = zwv[(size_t)cB.x * 32 + lane];
            uint2 u5 = zwv[(size_t)cB.y * 32 + lane];
            uint2 u6 = zwv[(size_t)cB.z * 32 + lane];
            uint2 u7 = zwv[(size_t)cB.w * 32 + lane];
            __half2 loA = __hadd2(
                __hadd2(*(const __half2*)&u0.x, *(const __half2*)&u1.x),
                __hadd2(*(const __half2*)&u2.x, *(const __half2*)&u3.x));
            __half2 hiA = __hadd2(
                __hadd2(*(const __half2*)&u0.y, *(const __half2*)&u1.y),
                __hadd2(*(const __half2*)&u2.y, *(const __half2*)&u3.y));
            __half2 loB = __hadd2(
                __hadd2(*(const __half2*)&u4.x, *(const __half2*)&u5.x),
                __hadd2(*(const __half2*)&u6.x, *(const __half2*)&u7.x));
            __half2 hiB = __hadd2(
                __hadd2(*(const __half2*)&u4.y, *(const __half2*)&u5.y),
                __hadd2(*(const __half2*)&u6.y, *(const __half2*)&u7.y));
            float2 fa = __half22float2(loA);
            float2 fb = __half22float2(hiA);
            float2 fc = __half22float2(loB);
            float2 fd = __half22float2(hiB);
            acc.x += fa.x + fc.x; acc.y += fa.y + fc.y;
            acc.z += fb.x + fd.x; acc.w += fb.y + fd.y;
        }
        for (; e + 4 <= e1; e += 4) {
            int4 cc = *(const int4*)&g_col[e];
            uint2 u0 = zwv[(size_t)cc.x * 32 + lane];
            uint2 u1 = zwv[(size_t)cc.y * 32 + lane];
            uint2 u2 = zwv[(size_t)cc.z * 32 + lane];
            uint2 u3 = zwv[(size_t)cc.w * 32 + lane];
            __half2 lo = __hadd2(
                __hadd2(*(const __half2*)&u0.x, *(const __half2*)&u1.x),
                __hadd2(*(const __half2*)&u2.x, *(const __half2*)&u3.x));
            __half2 hi = __hadd2(
                __hadd2(*(const __half2*)&u0.y, *(const __half2*)&u1.y),
                __hadd2(*(const __half2*)&u2.y, *(const __half2*)&u3.y));
            float2 flo = __half22float2(lo);
            float2 fhi = __half22float2(hi);
            acc.x += flo.x; acc.y += flo.y;
            acc.z += fhi.x; acc.w += fhi.y;
        }
        for (; e < e1; e++) {
            int s = g_col[e];
            uint2 u = zwv[(size_t)s * 32 + lane];
            float2 a = __half22float2(*(const __half2*)&u.x);
            float2 c = __half22float2(*(const __half2*)&u.y);
            acc.x += a.x; acc.y += a.y; acc.z += c.x; acc.w += c.y;
        }

        float4 b  = ((const float4*)bias)[lane];
        float4 al = ((const float4*)alpha)[lane];
        z0 = fmaf(acc.x, di, b.x);
        z1 = fmaf(acc.y, di, b.y);
        z2 = fmaf(acc.z, di, b.z);
        z3 = fmaf(acc.w, di, b.w);
        z0 = z0 > 0.0f ? z0 : al.x * z0;
        z1 = z1 > 0.0f ? z1 : al.y * z1;
        z2 = z2 > 0.0f ? z2 : al.z * z2;
        z3 = z3 > 0.0f ? z3 : al.w * z3;

        if (OUTHALF) {
            __half2 h[2];
            h[0] = __floats2half2_rn(z0, z1);
            h[1] = __floats2half2_rn(z2, z3);
            ((uint2*)zout)[(size_t)i * 32 + lane] = *(uint2*)h;
        } else {
            float4 out = {z0, z1, z2, z3};
            ((float4*)zout)[(size_t)i * 32 + lane] = out;
        }
        gi = batch[i];
    }

    if (lane == 0) sgi[wid] = gi;
    sred[wid][lane * 4 + 0] = z0;
    sred[wid][lane * 4 + 1] = z1;
    sred[wid][lane * 4 + 2] = z2;
    sred[wid][lane * 4 + 3] = z3;
    __syncthreads();

    int g0 = sgi[0];
    bool uni = (g0 >= 0);
    #pragma unroll
    for (int w = 1; w < 8; w++) uni = uni && (sgi[w] == g0);

    if (uni) {
        int f = threadIdx.x;
        if (f < 128) {
            float s = 0.f;
            #pragma unroll
            for (int w = 0; w < 8; w++) s += sred[w][f];
            atomicAdd(&pool[(size_t)g0 * 256 + f], s);
        }
    } else if (valid) {
        float* p = &pool[(size_t)gi * 256 + lane * 4];
        atomicAdd(p + 0, z0);
        atomicAdd(p + 1, z1);
        atomicAdd(p + 2, z2);
        atomicAdd(p + 3, z3);
    }
}

// ---------------- fusedA: count | W-prep | pool-zero -----------------------------
__global__ void __launch_bounds__(256) fusedA_kernel(
    const int* __restrict__ dst, int e,
    float* __restrict__ pool, int gsize,
    const float* __restrict__ W0, const float* __restrict__ W1,
    int CB, int PB) {
    int b = blockIdx.x;
    int tid = threadIdx.x;
    if (b < CB) {
        int i = b * 256 + tid;
        if (i < e) atomicAdd(&g_cnt[dst[i]], 1);
        return;
    }
    b -= CB;
    if (b < PB) {
        int idx = b * 256 + tid;
        int k = idx >> 7, nn = idx & 127;
        g_W0h[nn * 128 + k] = __float2half(W0[k * 128 + nn]);
        g_W1h[nn * 128 + k] = __float2half(W1[k * 128 + nn]);
        return;
    }
    b -= PB;
    int i = b * 256 + tid;
    if (i < gsize) pool[i] = 0.0f;
}

// ---------------- scan body (runs inside fusedB; 98 blocks, wave-1 resident) ----
__device__ __forceinline__ void scan_body(int n, int nb, int b) {
    __shared__ int ws[8];
    __shared__ int sadd;
    int tid = threadIdx.x;
    int lane = tid & 31, wid = tid >> 5;

    int base = b * SCHUNK + tid * 2;
    int v0 = base < n ? g_cnt[base] : 0;
    int v1 = base + 1 < n ? g_cnt[base + 1] : 0;
    int t = v0 + v1;
    int s = t;
    #pragma unroll
    for (int d = 16; d > 0; d >>= 1) s += __shfl_down_sync(0xFFFFFFFFu, s, d);
    if (lane == 0) ws[wid] = s;
    __syncthreads();
    if (tid == 0) {
        int tot = 0;
        #pragma unroll
        for (int w = 0; w < 8; w++) tot += ws[w];
        g_bsum[b] = tot;
        __threadfence();
        atomicAdd(&g_scan_ctr, 1);
        while (*(volatile int*)&g_scan_ctr < nb) __nanosleep(64);
    }
    __syncthreads();
    __threadfence();

    if (tid == 0) sadd = 0;
    __syncthreads();
    int part = 0;
    for (int j = tid; j < b; j += 256) part += g_bsum[j];
    #pragma unroll
    for (int d = 16; d > 0; d >>= 1) part += __shfl_down_sync(0xFFFFFFFFu, part, d);
    if (lane == 0 && part != 0) atomicAdd(&sadd, part);

    int x = t;
    #pragma unroll
    for (int d = 1; d < 32; d <<= 1) {
        int y = __shfl_up_sync(0xFFFFFFFFu, x, d);
        if (lane >= d) x += y;
    }
    if (lane == 31) ws[wid] = x;
    __syncthreads();
    int add = sadd;
    for (int w = 0; w < wid; w++) add += ws[w];
    int excl = x - t + add;
    if (base < n) {
        g_rowptr[base + 1] = excl + v0;
        g_cur[base] = excl;
        g_dinv[base] = rsqrtf((float)(v0 + 1));  // +1 self loop
        g_cnt[base] = 0;                         // restore invariant
    }
    if (base + 1 < n) {
        g_rowptr[base + 2] = excl + v0 + v1;
        g_cur[base + 1] = excl + v0;
        g_dinv[base + 1] = rsqrtf((float)(v1 + 1));
        g_cnt[base + 1] = 0;
    }
    if (b == 0 && tid == 0) g_rowptr[0] = 0;

    __syncthreads();
    if (tid == 0) {
        __threadfence();
        atomicAdd(&g_scan_done, 1);
    }
}

// ---------------- fusedB: scan(98) | gemm0(391) | fill(3125, waits scan) --------
__global__ void __launch_bounds__(256) fusedB_kernel(
    const int* __restrict__ src, const int* __restrict__ dst, int e,
    const float* __restrict__ A, const __half* __restrict__ Wh,
    __half* __restrict__ C, int n, int SB, int GB, int nb) {
    __shared__ __align__(16) __half As[128][40];
    __shared__ __align__(16) __half Bs[128][40];
    int b = blockIdx.x;
    if (b < SB) {
        scan_body(n, nb, b);
        return;
    }
    b -= SB;
    if (b < GB) {
        gemm_body_chunked<false>(As, Bs, A, nullptr, Wh, C, n, b * 128);
        return;
    }
    b -= GB;
    if (threadIdx.x == 0) {
        while (*(volatile int*)&g_scan_done < SB) __nanosleep(64);
    }
    __syncthreads();
    __threadfence();
    int i = b * 256 + threadIdx.x;
    if (i < e) {
        int pos = atomicAdd(&g_cur[dst[i]], 1);
        g_col[pos] = src[i];
    }
}

// ---------------- fusedC: gather0(GBLK) | gemm1(ntiles, per-tile dep) ------------
// gather block b produces z1 rows b*8..b*8+7 and publishes to g_tile_cnt[b>>4].
// gemm1 tile t waits for its min(16, GBLK-16t) producers, then computes
// zwh[128t..] = dinv * (z1 @ W1) with the chunked body.
__global__ void __launch_bounds__(256) fusedC_kernel(
    const __half* __restrict__ zws,     // gather input (layer-0 zw, scaled)
    const float* __restrict__ bias,
    const float* __restrict__ alpha,
    const int* __restrict__ batch,
    __half* __restrict__ z1h,           // gather out / gemm A
    float* __restrict__ pool,
    const __half* __restrict__ Wh,      // W1h
    __half* __restrict__ Cout,          // zwh (gemm out)
    int n, int GBLK) {
    __shared__ __align__(16) char sbuf[20480];  // union: gather red / gemm tiles
    int b = blockIdx.x;
    int tid = threadIdx.x;

    if (b < GBLK) {
        // reset scan counters for next launch (was gather0's job)
        if (b == 0 && tid == 0) {
            g_scan_ctr = 0;
            g_scan_done = 0;
        }
        float (*sred)[132] = (float(*)[132])sbuf;
        int* sgi = (int*)(sbuf + 8 * 132 * sizeof(float));
        gather_body<true>(zws, bias, alpha, batch, z1h, pool, n, b, sred, sgi);
        // publish z1h rows to the tile counter (syncthreads inside gather_body
        // already ran after stores; one more to cover the pool path)
        __syncthreads();
        if (tid == 0) {
            __threadfence();
            atomicAdd(&g_tile_cnt[b >> 4], 1);
        }
        return;
    }
    int t = b - GBLK;
    int target = GBLK - 16 * t;
    if (target > 16) target = 16;
    if (tid == 0) {
        while (*(volatile int*)&g_tile_cnt[t] < target) __nanosleep(64);
    }
    __syncthreads();
    __threadfence();
    __half (*As)[40] = (__half(*)[40])sbuf;
    __half (*Bs)[40] = (__half(*)[40])(sbuf + 128 * 40 * sizeof(__half));
    gemm_body_chunked<true>(As, Bs, nullptr, z1h, Wh, Cout, n, t * 128);
}

// ---------------- gather layer 1 (standalone; also resets tile counters) --------
__global__ void __launch_bounds__(256) gather1_kernel(
    const __half* __restrict__ zws,
    const float* __restrict__ bias,
    const float* __restrict__ alpha,
    const int* __restrict__ batch,
    float* __restrict__ zout,
    float* __restrict__ pool,
    int n, int ntiles) {
    __shared__ float sred[8][132];
    __shared__ int sgi[8];
    if ((int)blockIdx.x < ntiles && threadIdx.x == 0)
        g_tile_cnt[blockIdx.x] = 0;   // restore invariant for next launch
    gather_body<false>(zws, bias, alpha, batch, zout, pool, n, blockIdx.x,
                       sred, sgi);
}

// ---------------- launch ----------------------------------------------------------
extern "C" void kernel_launch(void* const* d_in, const int* in_sizes, int n_in,
                              void* d_out, int out_size) {
    const float* x      = (const float*)d_in[0];
    const int*   eidx   = (const int*)d_in[1];
    const int*   batch  = (const int*)d_in[2];
    const float* W0     = (const float*)d_in[3];
    const float* b0     = (const float*)d_in[4];
    const float* alpha0 = (const float*)d_in[5];
    const float* W1     = (const float*)d_in[6];
    const float* b1     = (const float*)d_in[7];
    const float* alpha1 = (const float*)d_in[8];

    int n = in_sizes[0] / HH;       // 50000
    int e = in_sizes[1] / 2;        // 800000
    const int* src = eidx;
    const int* dst = eidx + e;

    float* z2_out = (float*)d_out;                   // [n,128]
    float* g_pool = (float*)d_out + (size_t)n * HH;  // [G, 256]
    int gsize = out_size - n * HH;                   // 65536

    __half* zwh;  cudaGetSymbolAddress((void**)&zwh, g_zwh);
    __half* z1h;  cudaGetSymbolAddress((void**)&z1h, g_z1h);
    __half* W0h;  cudaGetSymbolAddress((void**)&W0h, g_W0h);
    __half* W1h;  cudaGetSymbolAddress((void**)&W1h, g_W1h);

    int nb = (n + SCHUNK - 1) / SCHUNK;          // 98
    int GB = (n + 127) / 128;                    // 391 (gemm tiles)
    int CB = (e + 255) / 256;                    // 3125
    int PB = 64;                                 // W prep blocks
    int ZB = (gsize + 255) / 256;                // 256
    int FB = CB;
    int gather_blocks = (n + 7) / 8;             // 6250

    // Phase A: degree count + W fp16 transpose + pool zero (all independent)
    fusedA_kernel<<<CB + PB + ZB, 256>>>(dst, e, g_pool, gsize, W0, W1, CB, PB);

    // Phase B: scan (wave 1) | GEMM0 (independent) | fill (waits on scan counter)
    fusedB_kernel<<<nb + GB + FB, 256>>>(src, dst, e, x, W0h, zwh, n, nb, GB, nb);

    // Phase C: gather0 | gemm1 (per-tile dataflow dependency)
    fusedC_kernel<<<gather_blocks + GB, 256>>>(
        zwh, b0, alpha0, batch, z1h, g_pool, W1h, zwh, n, gather_blocks);

    // Layer 1 aggregate (also resets tile counters)
    gather1_kernel<<<gather_blocks, 256>>>(
        zwh, b1, alpha1, batch, z2_out, g_pool + HH, n, GB);
}

// round 17
// speedup vs baseline: 1.5554x; 1.5554x over previous
#include <cuda_runtime.h>
#include <cuda_fp16.h>
#include <cstdint>

#define NN 50000
#define EE 800000
#define HH 128
#define GG 256
#define SCHUNK 512
#define MAXNB 128   // >= ceil(NN/SCHUNK)=98
#define FSTRIDE 136 // full-K smem row stride (halves): 68 words ≡ 4 mod 32 -> conflict-free
#define SMEM_FULL (2 * 128 * FSTRIDE * 2)  // 69632 bytes

// ---------------- scratch (device globals: no allocation allowed) -----------
__device__ __align__(16) __half g_zwh[NN * HH];   // dinv-scaled z @ W (fp16)
__device__ __align__(16) __half g_z1h[NN * HH];   // layer-1 activation (fp16)
__device__ __align__(16) __half g_W0h[HH * HH];   // W0 transposed [n][k] fp16
__device__ __align__(16) __half g_W1h[HH * HH];   // W1 transposed [n][k] fp16
__device__ __align__(16) float g_dinv[NN];        // 1/sqrt(deg)
__device__ __align__(16) int   g_cnt[NN];         // degree histogram (0 at launch entry)
__device__ __align__(16) int   g_cur[NN];         // fill cursor
__device__ __align__(16) int   g_rowptr[NN + 1];  // CSR row pointers (by dst)
__device__ __align__(16) int   g_col[EE];         // CSR column (src) — int4-read!
__device__ __align__(16) int   g_bsum[MAXNB];     // per-chunk sums
__device__ int   g_scan_ctr;        // scan-internal barrier (0 at launch entry)
__device__ int   g_scan_done;       // scan-complete counter (0 at launch entry)

// ---------------- fp16 MMA helper ----------------------------------------------
__device__ __forceinline__ void mma_f16(float c[4],
                                        uint32_t a0, uint32_t a1,
                                        uint32_t a2, uint32_t a3,
                                        uint32_t b0, uint32_t b1) {
    asm volatile(
        "mma.sync.aligned.m16n8k16.row.col.f32.f16.f16.f32 "
        "{%0,%1,%2,%3}, {%4,%5,%6,%7}, {%8,%9}, {%0,%1,%2,%3};"
        : "+f"(c[0]), "+f"(c[1]), "+f"(c[2]), "+f"(c[3])
        : "r"(a0), "r"(a1), "r"(a2), "r"(a3), "r"(b0), "r"(b1));
}

// ---------------- chunked fp16 GEMM body (used by fusedB / gemm0) ---------------
__device__ __forceinline__ void gemm_body_chunked(
    __half (*As)[40], __half (*Bs)[40],
    const float* __restrict__ Af,
    const __half* __restrict__ Wh,
    __half* __restrict__ C, int n, int m0) {
    int tid = threadIdx.x;
    int lane = tid & 31, wid = tid >> 5;
    int wm = wid >> 1;
    int wn = wid & 1;

    float acc[2][8][4];
    #pragma unroll
    for (int ms = 0; ms < 2; ms++)
        #pragma unroll
        for (int nt = 0; nt < 8; nt++)
            #pragma unroll
            for (int j = 0; j < 4; j++) acc[ms][nt][j] = 0.0f;

    int rq = lane >> 2;
    int kq = (lane & 3) * 2;

    for (int k0 = 0; k0 < 128; k0 += 32) {
        #pragma unroll
        for (int it = 0; it < 2; it++) {
            int f = tid + 256 * it;
            int row = f >> 2;
            int k8 = (f & 3) * 8;
            int rg = m0 + row;
            if (rg >= n) rg = n - 1;
            float4 a0 = *(const float4*)&Af[(size_t)rg * 128 + k0 + k8];
            float4 a1 = *(const float4*)&Af[(size_t)rg * 128 + k0 + k8 + 4];
            __half2 h[4];
            h[0] = __floats2half2_rn(a0.x, a0.y);
            h[1] = __floats2half2_rn(a0.z, a0.w);
            h[2] = __floats2half2_rn(a1.x, a1.y);
            h[3] = __floats2half2_rn(a1.z, a1.w);
            *(uint4*)&As[row][k8] = *(uint4*)h;
        }
        #pragma unroll
        for (int it = 0; it < 2; it++) {
            int f = tid + 256 * it;
            int nr = f >> 2;
            int k8 = (f & 3) * 8;
            uint4 v = *(const uint4*)&Wh[(size_t)nr * 128 + k0 + k8];
            *(uint4*)&Bs[nr][k8] = v;
        }
        __syncthreads();

        #pragma unroll
        for (int kk = 0; kk < 32; kk += 16) {
            uint32_t a[2][4];
            #pragma unroll
            for (int ms = 0; ms < 2; ms++) {
                int r = wm * 32 + ms * 16 + rq;
                a[ms][0] = *(const uint32_t*)&As[r][kk + kq];
                a[ms][1] = *(const uint32_t*)&As[r + 8][kk + kq];
                a[ms][2] = *(const uint32_t*)&As[r][kk + kq + 8];
                a[ms][3] = *(const uint32_t*)&As[r + 8][kk + kq + 8];
            }
            #pragma unroll
            for (int nt = 0; nt < 8; nt++) {
                int nc = wn * 64 + nt * 8 + rq;
                uint32_t b0 = *(const uint32_t*)&Bs[nc][kk + kq];
                uint32_t b1 = *(const uint32_t*)&Bs[nc][kk + kq + 8];
                #pragma unroll
                for (int ms = 0; ms < 2; ms++)
                    mma_f16(acc[ms][nt], a[ms][0], a[ms][1], a[ms][2], a[ms][3], b0, b1);
            }
        }
        __syncthreads();
    }

    __half2* Ch = (__half2*)C;
    #pragma unroll
    for (int ms = 0; ms < 2; ms++) {
        int r0 = m0 + wm * 32 + ms * 16 + rq;
        float di0 = (r0 < n) ? g_dinv[r0] : 0.0f;
        float di8 = (r0 + 8 < n) ? g_dinv[r0 + 8] : 0.0f;
        #pragma unroll
        for (int nt = 0; nt < 8; nt++) {
            int nc = wn * 64 + nt * 8 + (lane & 3) * 2;
            if (r0 < n)
                Ch[(size_t)r0 * 64 + (nc >> 1)] =
                    __floats2half2_rn(di0 * acc[ms][nt][0], di0 * acc[ms][nt][1]);
            if (r0 + 8 < n)
                Ch[(size_t)(r0 + 8) * 64 + (nc >> 1)] =
                    __floats2half2_rn(di8 * acc[ms][nt][2], di8 * acc[ms][nt][3]);
        }
    }
}

// ---------------- fusedA: count | W-prep | pool-zero -----------------------------
__global__ void __launch_bounds__(256) fusedA_kernel(
    const int* __restrict__ dst, int e,
    float* __restrict__ pool, int gsize,
    const float* __restrict__ W0, const float* __restrict__ W1,
    int CB, int PB) {
    int b = blockIdx.x;
    int tid = threadIdx.x;
    if (b < CB) {
        int i = b * 256 + tid;
        if (i < e) atomicAdd(&g_cnt[dst[i]], 1);
        return;
    }
    b -= CB;
    if (b < PB) {
        int idx = b * 256 + tid;
        int k = idx >> 7, nn = idx & 127;
        g_W0h[nn * 128 + k] = __float2half(W0[k * 128 + nn]);
        g_W1h[nn * 128 + k] = __float2half(W1[k * 128 + nn]);
        return;
    }
    b -= PB;
    int i = b * 256 + tid;
    if (i < gsize) pool[i] = 0.0f;
}

// ---------------- scan body (runs inside fusedB; 98 blocks, wave-1 resident) ----
__device__ __forceinline__ void scan_body(int n, int nb, int b) {
    __shared__ int ws[8];
    __shared__ int sadd;
    int tid = threadIdx.x;
    int lane = tid & 31, wid = tid >> 5;

    int base = b * SCHUNK + tid * 2;
    int v0 = base < n ? g_cnt[base] : 0;
    int v1 = base + 1 < n ? g_cnt[base + 1] : 0;
    int t = v0 + v1;
    int s = t;
    #pragma unroll
    for (int d = 16; d > 0; d >>= 1) s += __shfl_down_sync(0xFFFFFFFFu, s, d);
    if (lane == 0) ws[wid] = s;
    __syncthreads();
    if (tid == 0) {
        int tot = 0;
        #pragma unroll
        for (int w = 0; w < 8; w++) tot += ws[w];
        g_bsum[b] = tot;
        __threadfence();
        atomicAdd(&g_scan_ctr, 1);
        while (*(volatile int*)&g_scan_ctr < nb) __nanosleep(64);
    }
    __syncthreads();
    __threadfence();

    if (tid == 0) sadd = 0;
    __syncthreads();
    int part = 0;
    for (int j = tid; j < b; j += 256) part += g_bsum[j];
    #pragma unroll
    for (int d = 16; d > 0; d >>= 1) part += __shfl_down_sync(0xFFFFFFFFu, part, d);
    if (lane == 0 && part != 0) atomicAdd(&sadd, part);

    int x = t;
    #pragma unroll
    for (int d = 1; d < 32; d <<= 1) {
        int y = __shfl_up_sync(0xFFFFFFFFu, x, d);
        if (lane >= d) x += y;
    }
    if (lane == 31) ws[wid] = x;
    __syncthreads();
    int add = sadd;
    for (int w = 0; w < wid; w++) add += ws[w];
    int excl = x - t + add;
    if (base < n) {
        g_rowptr[base + 1] = excl + v0;
        g_cur[base] = excl;
        g_dinv[base] = rsqrtf((float)(v0 + 1));  // +1 self loop
        g_cnt[base] = 0;                         // restore invariant
    }
    if (base + 1 < n) {
        g_rowptr[base + 2] = excl + v0 + v1;
        g_cur[base + 1] = excl + v0;
        g_dinv[base + 1] = rsqrtf((float)(v1 + 1));
        g_cnt[base + 1] = 0;
    }
    if (b == 0 && tid == 0) g_rowptr[0] = 0;

    __syncthreads();
    if (tid == 0) {
        __threadfence();
        atomicAdd(&g_scan_done, 1);
    }
}

// ---------------- fusedB: scan(98) | gemm0(391) | fill(3125, waits scan) --------
__global__ void __launch_bounds__(256) fusedB_kernel(
    const int* __restrict__ src, const int* __restrict__ dst, int e,
    const float* __restrict__ A, const __half* __restrict__ Wh,
    __half* __restrict__ C, int n, int SB, int GB, int nb) {
    __shared__ __align__(16) __half As[128][40];
    __shared__ __align__(16) __half Bs[128][40];
    int b = blockIdx.x;
    if (b < SB) {
        scan_body(n, nb, b);
        return;
    }
    b -= SB;
    if (b < GB) {
        gemm_body_chunked(As, Bs, A, Wh, C, n, b * 128);
        return;
    }
    b -= GB;
    // fill: wait for all scan blocks
    if (threadIdx.x == 0) {
        while (*(volatile int*)&g_scan_done < SB) __nanosleep(64);
    }
    __syncthreads();
    __threadfence();
    int i = b * 256 + threadIdx.x;
    if (i < e) {
        int pos = atomicAdd(&g_cur[dst[i]], 1);
        g_col[pos] = src[i];
    }
}

// ---------------- GEMM layer 1: full-K resident tiles (dynamic smem) ------------
__global__ void __launch_bounds__(256) gemm1_kernel(
    const __half* __restrict__ Ah, const __half* __restrict__ Wh,
    __half* __restrict__ C, int n) {
    extern __shared__ __align__(16) __half smem[];
    __half (*As)[FSTRIDE] = (__half(*)[FSTRIDE])smem;
    __half (*Bs)[FSTRIDE] = (__half(*)[FSTRIDE])(smem + 128 * FSTRIDE);

    int tid = threadIdx.x;
    int lane = tid & 31, wid = tid >> 5;
    int wm = wid >> 1;
    int wn = wid & 1;
    int m0 = blockIdx.x * 128;

    #pragma unroll
    for (int it = 0; it < 8; it++) {
        int f = tid + 256 * it;            // 0..2047
        int row = f >> 4;
        int u = (f & 15) * 8;
        int rg = m0 + row;
        if (rg >= n) rg = n - 1;
        *(uint4*)&As[row][u] = *(const uint4*)&Ah[(size_t)rg * 128 + u];
        *(uint4*)&Bs[row][u] = *(const uint4*)&Wh[(size_t)row * 128 + u];
    }
    __syncthreads();

    float acc[2][8][4];
    #pragma unroll
    for (int ms = 0; ms < 2; ms++)
        #pragma unroll
        for (int nt = 0; nt < 8; nt++)
            #pragma unroll
            for (int j = 0; j < 4; j++) acc[ms][nt][j] = 0.0f;

    int rq = lane >> 2;
    int kq = (lane & 3) * 2;

    #pragma unroll
    for (int kk = 0; kk < 128; kk += 16) {
        uint32_t a[2][4];
        #pragma unroll
        for (int ms = 0; ms < 2; ms++) {
            int r = wm * 32 + ms * 16 + rq;
            a[ms][0] = *(const uint32_t*)&As[r][kk + kq];
            a[ms][1] = *(const uint32_t*)&As[r + 8][kk + kq];
            a[ms][2] = *(const uint32_t*)&As[r][kk + kq + 8];
            a[ms][3] = *(const uint32_t*)&As[r + 8][kk + kq + 8];
        }
        #pragma unroll
        for (int nt = 0; nt < 8; nt++) {
            int nc = wn * 64 + nt * 8 + rq;
            uint32_t b0 = *(const uint32_t*)&Bs[nc][kk + kq];
            uint32_t b1 = *(const uint32_t*)&Bs[nc][kk + kq + 8];
            #pragma unroll
            for (int ms = 0; ms < 2; ms++)
                mma_f16(acc[ms][nt], a[ms][0], a[ms][1], a[ms][2], a[ms][3], b0, b1);
        }
    }

    __half2* Ch = (__half2*)C;
    #pragma unroll
    for (int ms = 0; ms < 2; ms++) {
        int r0 = m0 + wm * 32 + ms * 16 + rq;
        float di0 = (r0 < n) ? g_dinv[r0] : 0.0f;
        float di8 = (r0 + 8 < n) ? g_dinv[r0 + 8] : 0.0f;
        #pragma unroll
        for (int nt = 0; nt < 8; nt++) {
            int nc = wn * 64 + nt * 8 + (lane & 3) * 2;
            if (r0 < n)
                Ch[(size_t)r0 * 64 + (nc >> 1)] =
                    __floats2half2_rn(di0 * acc[ms][nt][0], di0 * acc[ms][nt][1]);
            if (r0 + 8 < n)
                Ch[(size_t)(r0 + 8) * 64 + (nc >> 1)] =
                    __floats2half2_rn(di8 * acc[ms][nt][2], di8 * acc[ms][nt][3]);
        }
    }
}

// ---------------- gather (dinv-scaled fp16 in) + bias + PReLU + pool ------------
template <bool OUTHALF>
__global__ void __launch_bounds__(256) gather_kernel(
    const __half* __restrict__ zws,
    const float* __restrict__ bias,
    const float* __restrict__ alpha,
    const int* __restrict__ batch,
    void* __restrict__ zout,
    float* __restrict__ pool,
    int n, int reset) {
    __shared__ float sred[8][132];
    __shared__ int sgi[8];
    if (reset && blockIdx.x == 0 && threadIdx.x == 0) {
        g_scan_ctr = 0;
        g_scan_done = 0;
    }
    int wid = threadIdx.x >> 5, lane = threadIdx.x & 31;
    int i = blockIdx.x * 8 + wid;
    bool valid = i < n;

    float z0 = 0.f, z1 = 0.f, z2 = 0.f, z3 = 0.f;
    int gi = -1;

    if (valid) {
        const uint2* __restrict__ zwv = (const uint2*)zws;  // 4 halves per lane
        float di = g_dinv[i];

        uint2 sv = zwv[(size_t)i * 32 + lane];
        float2 f0 = __half22float2(*(const __half2*)&sv.x);
        float2 f1 = __half22float2(*(const __half2*)&sv.y);
        float4 acc = {f0.x, f0.y, f1.x, f1.y};

        int e0 = g_rowptr[i], e1 = g_rowptr[i + 1];
        int e = e0;
        for (; e < e1 && (e & 3); e++) {
            int s = g_col[e];
            uint2 u = zwv[(size_t)s * 32 + lane];
            float2 a = __half22float2(*(const __half2*)&u.x);
            float2 c = __half22float2(*(const __half2*)&u.y);
            acc.x += a.x; acc.y += a.y; acc.z += c.x; acc.w += c.y;
        }
        for (; e + 8 <= e1; e += 8) {
            int4 cA = *(const int4*)&g_col[e];
            int4 cB = *(const int4*)&g_col[e + 4];
            uint2 u0 = zwv[(size_t)cA.x * 32 + lane];
            uint2 u1 = zwv[(size_t)cA.y * 32 + lane];
            uint2 u2 = zwv[(size_t)cA.z * 32 + lane];
            uint2 u3 = zwv[(size_t)cA.w * 32 + lane];
            uint2 u4 = zwv[(size_t)cB.x * 32 + lane];
            uint2 u5 = zwv[(size_t)cB.y * 32 + lane];
            uint2 u6 = zwv[(size_t)cB.z * 32 + lane];
            uint2 u7 = zwv[(size_t)cB.w * 32 + lane];
            __half2 loA = __hadd2(
                __hadd2(*(const __half2*)&u0.x, *(const __half2*)&u1.x),
                __hadd2(*(const __half2*)&u2.x, *(const __half2*)&u3.x));
            __half2 hiA = __hadd2(
                __hadd2(*(const __half2*)&u0.y, *(const __half2*)&u1.y),
                __hadd2(*(const __half2*)&u2.y, *(const __half2*)&u3.y));
            __half2 loB = __hadd2(
                __hadd2(*(const __half2*)&u4.x, *(const __half2*)&u5.x),
                __hadd2(*(const __half2*)&u6.x, *(const __half2*)&u7.x));
            __half2 hiB = __hadd2(
                __hadd2(*(const __half2*)&u4.y, *(const __half2*)&u5.y),
                __hadd2(*(const __half2*)&u6.y, *(const __half2*)&u7.y));
            float2 fa = __half22float2(loA);
            float2 fb = __half22float2(hiA);
            float2 fc = __half22float2(loB);
            float2 fd = __half22float2(hiB);
            acc.x += fa.x + fc.x; acc.y += fa.y + fc.y;
            acc.z += fb.x + fd.x; acc.w += fb.y + fd.y;
        }
        for (; e + 4 <= e1; e += 4) {
            int4 cc = *(const int4*)&g_col[e];
            uint2 u0 = zwv[(size_t)cc.x * 32 + lane];
            uint2 u1 = zwv[(size_t)cc.y * 32 + lane];
            uint2 u2 = zwv[(size_t)cc.z * 32 + lane];
            uint2 u3 = zwv[(size_t)cc.w * 32 + lane];
            __half2 lo = __hadd2(
                __hadd2(*(const __half2*)&u0.x, *(const __half2*)&u1.x),
                __hadd2(*(const __half2*)&u2.x, *(const __half2*)&u3.x));
            __half2 hi = __hadd2(
                __hadd2(*(const __half2*)&u0.y, *(const __half2*)&u1.y),
                __hadd2(*(const __half2*)&u2.y, *(const __half2*)&u3.y));
            float2 flo = __half22float2(lo);
            float2 fhi = __half22float2(hi);
            acc.x += flo.x; acc.y += flo.y;
            acc.z += fhi.x; acc.w += fhi.y;
        }
        for (; e < e1; e++) {
            int s = g_col[e];
            uint2 u = zwv[(size_t)s * 32 + lane];
            float2 a = __half22float2(*(const __half2*)&u.x);
            float2 c = __half22float2(*(const __half2*)&u.y);
            acc.x += a.x; acc.y += a.y; acc.z += c.x; acc.w += c.y;
        }

        float4 b  = ((const float4*)bias)[lane];
        float4 al = ((const float4*)alpha)[lane];
        z0 = fmaf(acc.x, di, b.x);
        z1 = fmaf(acc.y, di, b.y);
        z2 = fmaf(acc.z, di, b.z);
        z3 = fmaf(acc.w, di, b.w);
        z0 = z0 > 0.0f ? z0 : al.x * z0;
        z1 = z1 > 0.0f ? z1 : al.y * z1;
        z2 = z2 > 0.0f ? z2 : al.z * z2;
        z3 = z3 > 0.0f ? z3 : al.w * z3;

        if (OUTHALF) {
            __half2 h[2];
            h[0] = __floats2half2_rn(z0, z1);
            h[1] = __floats2half2_rn(z2, z3);
            ((uint2*)zout)[(size_t)i * 32 + lane] = *(uint2*)h;
        } else {
            float4 out = {z0, z1, z2, z3};
            ((float4*)zout)[(size_t)i * 32 + lane] = out;
        }
        gi = batch[i];
    }

    if (lane == 0) sgi[wid] = gi;
    sred[wid][lane * 4 + 0] = z0;
    sred[wid][lane * 4 + 1] = z1;
    sred[wid][lane * 4 + 2] = z2;
    sred[wid][lane * 4 + 3] = z3;
    __syncthreads();

    int g0 = sgi[0];
    bool uni = (g0 >= 0);
    #pragma unroll
    for (int w = 1; w < 8; w++) uni = uni && (sgi[w] == g0);

    if (uni) {
        int f = threadIdx.x;
        if (f < 128) {
            float s = 0.f;
            #pragma unroll
            for (int w = 0; w < 8; w++) s += sred[w][f];
            atomicAdd(&pool[(size_t)g0 * 256 + f], s);
        }
    } else if (valid) {
        float* p = &pool[(size_t)gi * 256 + lane * 4];
        atomicAdd(p + 0, z0);
        atomicAdd(p + 1, z1);
        atomicAdd(p + 2, z2);
        atomicAdd(p + 3, z3);
    }
}

// ---------------- launch ----------------------------------------------------------
extern "C" void kernel_launch(void* const* d_in, const int* in_sizes, int n_in,
                              void* d_out, int out_size) {
    const float* x      = (const float*)d_in[0];
    const int*   eidx   = (const int*)d_in[1];
    const int*   batch  = (const int*)d_in[2];
    const float* W0     = (const float*)d_in[3];
    const float* b0     = (const float*)d_in[4];
    const float* alpha0 = (const float*)d_in[5];
    const float* W1     = (const float*)d_in[6];
    const float* b1     = (const float*)d_in[7];
    const float* alpha1 = (const float*)d_in[8];

    int n = in_sizes[0] / HH;       // 50000
    int e = in_sizes[1] / 2;        // 800000
    const int* src = eidx;
    const int* dst = eidx + e;

    float* z2_out = (float*)d_out;                   // [n,128]
    float* g_pool = (float*)d_out + (size_t)n * HH;  // [G, 256]
    int gsize = out_size - n * HH;                   // 65536

    __half* zwh;  cudaGetSymbolAddress((void**)&zwh, g_zwh);
    __half* z1h;  cudaGetSymbolAddress((void**)&z1h, g_z1h);
    __half* W0h;  cudaGetSymbolAddress((void**)&W0h, g_W0h);
    __half* W1h;  cudaGetSymbolAddress((void**)&W1h, g_W1h);

    int nb = (n + SCHUNK - 1) / SCHUNK;          // 98
    int GB = (n + 127) / 128;                    // 391
    int CB = (e + 255) / 256;                    // 3125
    int PB = 64;                                 // W prep blocks
    int ZB = (gsize + 255) / 256;                // 256
    int FB = CB;
    int gather_blocks = (n + 7) / 8;

    // allow 68KB dynamic smem for the full-K GEMM (idempotent, capture-safe)
    cudaFuncSetAttribute(gemm1_kernel,
                         cudaFuncAttributeMaxDynamicSharedMemorySize, SMEM_FULL);

    // Phase A: degree count + W fp16 transpose + pool zero (all independent)
    fusedA_kernel<<<CB + PB + ZB, 256>>>(dst, e, g_pool, gsize, W0, W1, CB, PB);

    // Phase B: scan (wave 1) | GEMM0 (independent) | fill (waits on scan counter)
    fusedB_kernel<<<nb + GB + FB, 256>>>(src, dst, e, x, W0h, zwh, n, nb, GB, nb);

    // Layer 0 aggregate (also resets counters); writes z1 as fp16
    gather_kernel<true><<<gather_blocks, 256>>>(
        zwh, b0, alpha0, batch, z1h, g_pool, n, 1);
    // Layer 1 (full-K resident GEMM)
    gemm1_kernel<<<GB, 256, SMEM_FULL>>>(z1h, W1h, zwh, n);
    gather_kernel<false><<<gather_blocks, 256>>>(
        zwh, b1, alpha1, batch, z2_out, g_pool + HH, n, 0);
}